// round 3
// baseline (speedup 1.0000x reference)
#include <cuda_runtime.h>

// GARCH(1,1): h[t] = (omega + alpha*r[t-1]^2) + beta*h[t-1], h[0] = var(r, ddof=1)
// out[0..n) = sqrt(h), out[n..2n) = h
//
// Single fused kernel. beta<1 => contractive recurrence (beta^256 ~ 8e-19):
// blocks compute the zero-state particular solution h_hat on tiles with a
// 256-elem warm-up halo; intra-block stitch is EXACT (Hillis-Steele with
// multipliers beta^(32*2^k)). True h[t] = h_hat[t] + beta^t*h0; the beta^t*h0
// term only matters for t < ~100 and is patched by the LAST block to finish
// (ticket pattern), which also reduces the fp32 variance partials. Driver +
// variance math uses packed f32x2; sqrt is sqrt.approx (1 MUFU op).

#define TPB   256
#define CPT   32
#define TILE  (TPB*CPT)        // 8192
#define HALO  256
#define OPB   (TILE - HALO)    // 7936 outputs per block, 4-aligned
#define QOUT  (OPB/4)          // 1984
#define FIXN  256
#define MAXB  4096

__device__ double   g_psum[MAXB];
__device__ double   g_psumsq[MAXB];
__device__ unsigned g_ticket = 0;

__device__ __forceinline__ int padidx(int k) { return k + (k >> 5); }

__device__ __forceinline__ float fsqrt_ap(float x) {
    float y; asm("sqrt.approx.f32 %0, %1;" : "=f"(y) : "f"(x)); return y;
}
// packed f32x2 (sm_100+)
__device__ __forceinline__ unsigned long long pk2(float lo, float hi) {
    unsigned long long d;
    asm("mov.b64 %0, {%1, %2};" : "=l"(d) : "r"(__float_as_uint(lo)), "r"(__float_as_uint(hi)));
    return d;
}
__device__ __forceinline__ void upk2(unsigned long long v, float& lo, float& hi) {
    unsigned a, b; asm("mov.b64 {%0, %1}, %2;" : "=r"(a), "=r"(b) : "l"(v));
    lo = __uint_as_float(a); hi = __uint_as_float(b);
}
__device__ __forceinline__ unsigned long long mul2(unsigned long long a, unsigned long long b) {
    unsigned long long d; asm("mul.rn.f32x2 %0, %1, %2;" : "=l"(d) : "l"(a), "l"(b)); return d;
}
__device__ __forceinline__ unsigned long long add2(unsigned long long a, unsigned long long b) {
    unsigned long long d; asm("add.rn.f32x2 %0, %1, %2;" : "=l"(d) : "l"(a), "l"(b)); return d;
}
__device__ __forceinline__ unsigned long long fma2(unsigned long long a, unsigned long long b, unsigned long long c) {
    unsigned long long d; asm("fma.rn.f32x2 %0, %1, %2, %3;" : "=l"(d) : "l"(a), "l"(b), "l"(c)); return d;
}

__global__ void __launch_bounds__(TPB)
garch_fused(const float* __restrict__ r,
            const float* __restrict__ omega_p,
            const float* __restrict__ alpha_p,
            const float* __restrict__ beta_p,
            float* __restrict__ out,
            int n, int nblocks, int write_h)
{
    __shared__ __align__(16) float bpad[TILE + TILE/32];
    __shared__ float  sscan[TPB];
    __shared__ float  powtab[CPT];          // beta^(j+1)
    __shared__ double wsum[TPB/32], wsq[TPB/32];
    __shared__ unsigned s_ticket;
    __shared__ float  sh0;

    const int   tid   = threadIdx.x;
    const int   b     = blockIdx.x;
    const float omega = *omega_p;
    const float alpha = *alpha_p;
    const float beta  = *beta_p;

    // outputs: t in [b*OPB, b*OPB+OPB) ∩ [0,n). tile index k = t - t0.
    const long long t0 = (long long)b * OPB - HALO;   // k=0 <-> t=t0
    const long long A  = t0 - 1;                      // driver r index: g = A + k

    float vs = 0.0f, vq = 0.0f;
    unsigned long long vs2 = 0ull, vq2 = 0ull;

    const bool fast = (b >= 1) && ((long long)(b + 1) * OPB <= (long long)n)
                      && ((n & 3) == 0);

    // ---- Phase 1: drivers b[k] = omega + alpha*r[g]^2, variance partials ----
    if (fast) {
        const float4* __restrict__ r4 = (const float4*)(r + (A - 3)); // 16B aligned
        const unsigned long long alpha2 = pk2(alpha, alpha);
        const unsigned long long omega2 = pk2(omega, omega);
        #pragma unroll
        for (int it = 0; it < 8; ++it) {
            int q = tid + it * TPB;
            float4 v = r4[q];
            int k0 = 4 * q - 3;
            if (it == 0) {                       // edge: k may be <0 / <HALO
                #pragma unroll
                for (int e = 0; e < 4; ++e) {
                    int k = k0 + e;
                    float rv = (e == 0) ? v.x : (e == 1) ? v.y : (e == 2) ? v.z : v.w;
                    if (k >= 0) {
                        float rr = rv * rv;
                        bpad[padidx(k)] = fmaf(alpha, rr, omega);
                        if (k >= HALO) { vs += rv; vq += rr; }
                    }
                }
            } else {                              // packed f32x2 math
                unsigned long long v01 = pk2(v.x, v.y), v23 = pk2(v.z, v.w);
                unsigned long long rr01 = mul2(v01, v01), rr23 = mul2(v23, v23);
                unsigned long long b01 = fma2(alpha2, rr01, omega2);
                unsigned long long b23 = fma2(alpha2, rr23, omega2);
                vs2 = add2(vs2, v01);  vs2 = add2(vs2, v23);
                vq2 = add2(vq2, rr01); vq2 = add2(vq2, rr23);
                float x0, x1, x2, x3;
                upk2(b01, x0, x1); upk2(b23, x2, x3);
                bpad[padidx(k0 + 0)] = x0;
                bpad[padidx(k0 + 1)] = x1;
                bpad[padidx(k0 + 2)] = x2;
                bpad[padidx(k0 + 3)] = x3;
            }
        }
        if (tid < 3) {                            // top 3 elements k=8189..8191
            int k = TILE - 3 + tid;
            float rv = r[A + k];
            float rr = rv * rv;
            bpad[padidx(k)] = fmaf(alpha, rr, omega);
            vs += rv; vq += rr;
        }
    } else {
        #pragma unroll 4
        for (int it = 0; it < TILE / TPB; ++it) {
            int k = tid + it * TPB;
            long long g = A + k;
            float bb = 0.0f;
            if (g >= 0 && g <= (long long)n - 2) {
                float rv = r[g];
                float rr = rv * rv;
                bb = fmaf(alpha, rr, omega);
                if (k >= HALO) { vs += rv; vq += rr; }
            }
            bpad[padidx(k)] = bb;
        }
    }
    if (b == 0 && tid == 0) {                     // r[n-1]: variance only
        float rv = r[n - 1];
        vs += rv; vq = fmaf(rv, rv, vq);
    }
    __syncthreads();

    // ---- Phase 2: per-thread serial recurrence from zero state (in place) ----
    {
        float h = 0.0f;
        const int base = 33 * tid;                // padidx(tid*32)
        #pragma unroll
        for (int j = 0; j < CPT; ++j) {
            h = fmaf(beta, h, bpad[base + j]);
            bpad[base + j] = h;                   // p[j] stays in shared
        }
        sscan[tid] = h;
    }
    if (tid < CPT) {                              // powtab[j] = beta^(j+1)
        float p = 1.0f, bb = beta; int e = tid + 1;
        while (e) { if (e & 1) p *= bb; bb *= bb; e >>= 1; }
        powtab[tid] = p;
    }
    __syncthreads();

    // ---- Phase 3: exact stitch S_i = E_i + beta^32 * S_{i-1} ----
    float b2 = beta * beta, b4 = b2 * b2, b8 = b4 * b4, b16 = b8 * b8;
    float mpow = b16 * b16;                       // beta^32
    #pragma unroll
    for (int d = 1; d < TPB; d <<= 1) {
        float v  = sscan[tid];
        float lo = (tid >= d) ? sscan[tid - d] : 0.0f;
        __syncthreads();
        sscan[tid] = fmaf(mpow, lo, v);
        mpow *= mpow;
        __syncthreads();
    }

    // ---- Phase 4: apply carry at read, vectorized stores ----
    if (fast) {
        #pragma unroll
        for (int it = 0; it < 8; ++it) {
            int q = tid + it * TPB;
            if (q < QOUT) {
                int k  = HALO + 4 * q;
                int c  = k >> 5;                  // >= 8 here
                float cy = sscan[c - 1];
                int pb = padidx(k);               // 4 consecutive, no pad cross
                int pj = k & 31;
                float h0 = fmaf(powtab[pj + 0], cy, bpad[pb + 0]);
                float h1 = fmaf(powtab[pj + 1], cy, bpad[pb + 1]);
                float h2 = fmaf(powtab[pj + 2], cy, bpad[pb + 2]);
                float h3 = fmaf(powtab[pj + 3], cy, bpad[pb + 3]);
                long long t = (long long)b * OPB + 4 * (long long)q;
                float4 sv = make_float4(fsqrt_ap(h0), fsqrt_ap(h1),
                                        fsqrt_ap(h2), fsqrt_ap(h3));
                *(float4*)(out + t) = sv;
                if (write_h) *(float4*)(out + n + t) = make_float4(h0, h1, h2, h3);
            }
        }
    } else {
        #pragma unroll 4
        for (int it = 0; it < TILE / TPB; ++it) {
            int k = tid + it * TPB;
            if (k < HALO) continue;
            long long t = t0 + k;
            if (t < (long long)n) {
                int c = k >> 5;
                float cy = (c > 0) ? sscan[c - 1] : 0.0f;
                float h = fmaf(powtab[k & 31], cy, bpad[padidx(k)]);
                out[t] = fsqrt_ap(h);
                if (write_h) out[(long long)n + t] = h;
            }
        }
    }

    // ---- Phase 5: variance reduce -> per-block slot ----
    {
        float a_, b_;
        upk2(vs2, a_, b_); vs += a_ + b_;
        upk2(vq2, a_, b_); vq += a_ + b_;
    }
    unsigned msk = 0xFFFFFFFFu;
    #pragma unroll
    for (int off = 16; off; off >>= 1) {
        vs += __shfl_down_sync(msk, vs, off);
        vq += __shfl_down_sync(msk, vq, off);
    }
    const int wid = tid >> 5, lane = tid & 31;
    if (lane == 0) { wsum[wid] = (double)vs; wsq[wid] = (double)vq; }
    __syncthreads();
    if (tid == 0) {
        double a = 0.0, q = 0.0;
        #pragma unroll
        for (int w = 0; w < TPB / 32; ++w) { a += wsum[w]; q += wsq[w]; }
        g_psum[b]   = a;
        g_psumsq[b] = q;
    }

    // ---- Phase 6: last-block ticket -> fused fixup ----
    __syncthreads();
    __threadfence();                              // every thread fences its STGs
    if (tid == 0) s_ticket = atomicAdd(&g_ticket, 1u);
    __syncthreads();
    if (s_ticket != (unsigned)(nblocks - 1)) return;

    if (tid == 0) g_ticket = 0;                   // reset for graph replays

    // deterministic reduction of per-block partials (bpad reused as scratch)
    double* red  = (double*)bpad;
    double* red2 = red + TPB;
    {
        double a = 0.0, q = 0.0;
        for (int i = tid; i < nblocks; i += TPB) { a += g_psum[i]; q += g_psumsq[i]; }
        red[tid] = a; red2[tid] = q;
    }
    __syncthreads();
    for (int s = TPB / 2; s; s >>= 1) {
        if (tid < s) { red[tid] += red[tid + s]; red2[tid] += red2[tid + s]; }
        __syncthreads();
    }
    if (tid == 0) {
        double S = red[0], Q = red2[0];
        sh0 = (float)((Q - S * S / (double)n) / (double)(n - 1));
    }
    __syncthreads();

    const float h0v = sh0;
    const int   lim = (FIXN < n) ? FIXN : n;
    if (write_h) {
        // h[t] = h_hat[t] + beta^t * h0 (linearity); h_hat is in out[n+t]
        for (int t = tid; t < lim; t += TPB) {
            float bp = 1.0f, bb = beta; int e = t;
            while (e) { if (e & 1) bp *= bb; bb *= bb; e >>= 1; }
            float hh = (t == 0) ? h0v : fmaf(bp, h0v, out[(long long)n + t]);
            out[(long long)n + t] = hh;
            out[t] = fsqrt_ap(hh);
        }
    } else {
        if (tid == 0) {                           // rare fallback: serial prefix
            float h = h0v;
            out[0] = fsqrt_ap(h);
            for (int t = 1; t < lim; ++t) {
                float rv = r[t - 1];
                h = fmaf(beta, h, fmaf(alpha * rv, rv, omega));
                out[t] = fsqrt_ap(h);
            }
        }
    }
}

extern "C" void kernel_launch(void* const* d_in, const int* in_sizes, int n_in,
                              void* d_out, int out_size)
{
    const float* r  = (const float*)d_in[0];
    const float* om = (const float*)d_in[1];
    const float* al = (const float*)d_in[2];
    const float* be = (const float*)d_in[3];
    float* out = (float*)d_out;

    const int n = in_sizes[0];
    const int write_h = (out_size >= 2 * n) ? 1 : 0;

    int nblocks = (n + OPB - 1) / OPB;
    if (nblocks < 1)    nblocks = 1;
    if (nblocks > MAXB) nblocks = MAXB;

    garch_fused<<<nblocks, TPB>>>(r, om, al, be, out, n, nblocks, write_h);
}